// round 6
// baseline (speedup 1.0000x reference)
#include <cuda_runtime.h>
#include <cuda_bf16.h>
#include <math.h>
#include <stdint.h>

#define Bq 128
#define Lq 64
#define Tq 48
#define Eq 512
#define Hq 512
#define Vq 32000
#define G4 2048
#define KP 512
#define NTILES 250           // logits N tiles (32000/128)
#define LSTRIDE 72
#define HB (Bq * Hq)
#define NLBLK 132            // logits group size

// ---------------- fp32 scratch ----------------
__device__ float g_G0[Bq * Lq * G4];
__device__ float g_c1[HB], g_c2[HB];
__device__ float g_S[Bq * Lq * Hq];
__device__ float g_dh[HB], g_dc[HB];
__device__ float g_nllbuf[(Tq - 1) * Bq];
__device__ float g_part[NTILES * Bq];
__device__ float g_tgtlogit[Bq];

// ---------------- bf16 weights ----------------
__device__ __nv_bfloat16 g_Wih0b[G4 * KP], g_Whh0b[G4 * KP];
__device__ __nv_bfloat16 g_Wih1b[G4 * KP], g_Whh1b[G4 * KP];
__device__ __nv_bfloat16 g_dWihb[G4 * 1024], g_dWhhb[G4 * KP];
__device__ __nv_bfloat16 g_hidWb[Hq * 1024], g_initWb[Hq * 1024];
__device__ __nv_bfloat16 g_srcEmbB[Vq * Eq], g_trgEmbB[Vq * Eq];
__device__ __nv_bfloat16 g_outWb[Vq * KP];

// ---------------- bf16 states ----------------
__device__ __nv_bfloat16 g_h1b[2][HB], g_h2b[2][HB], g_dhb[2][HB];
__device__ __nv_bfloat16 g_nh1b[HB];
__device__ __nv_bfloat16 g_c1b[HB], g_c2b[HB];
__device__ __nv_bfloat16 g_ctxb[HB];
__device__ __nv_bfloat16 g_avh[2][HB];

// ---------------- sync state (zeroed each launch) ----------------
// [0]=enc bar, [8]=decR bar, [16]=decL bar, [24]=r_done, [32]=l_done
__device__ __align__(128) unsigned g_sync[64];

// ---------------- MMA helpers ----------------
__device__ __forceinline__ void ldsm4(unsigned int* r, unsigned int addr) {
    asm volatile("ldmatrix.sync.aligned.m8n8.x4.shared.b16 {%0,%1,%2,%3}, [%4];"
                 : "=r"(r[0]), "=r"(r[1]), "=r"(r[2]), "=r"(r[3]) : "r"(addr));
}
__device__ __forceinline__ void ldsm2(unsigned int* r, unsigned int addr) {
    asm volatile("ldmatrix.sync.aligned.m8n8.x2.shared.b16 {%0,%1}, [%2];"
                 : "=r"(r[0]), "=r"(r[1]) : "r"(addr));
}
__device__ __forceinline__ void mma16816(float* c, const unsigned int* a, const unsigned int* b) {
    asm volatile("mma.sync.aligned.m16n8k16.row.col.f32.bf16.bf16.f32 "
                 "{%0,%1,%2,%3}, {%4,%5,%6,%7}, {%8,%9}, {%0,%1,%2,%3};"
                 : "+f"(c[0]), "+f"(c[1]), "+f"(c[2]), "+f"(c[3])
                 : "r"(a[0]), "r"(a[1]), "r"(a[2]), "r"(a[3]), "r"(b[0]), "r"(b[1]));
}

// ---------------- barriers / flags ----------------
__device__ __forceinline__ void gbar(unsigned* cnt, unsigned target) {
    __threadfence();
    __syncthreads();
    if (threadIdx.x == 0) {
        atomicAdd(cnt, 1u);
        while (*((volatile unsigned*)cnt) < target) __nanosleep(32);
    }
    __syncthreads();
    __threadfence();
}
__device__ __forceinline__ void wait_ge(unsigned* flag, unsigned v) {
    if (threadIdx.x == 0) {
        while (*((volatile unsigned*)flag) < v) __nanosleep(64);
    }
    __syncthreads();
    __threadfence();
}
__device__ __forceinline__ void set_flag(unsigned* flag, unsigned v) {
    __threadfence();
    atomicMax(flag, v);
}

// ============================================================
// gates-layout MMA: M=128, this block's 32 cols of each of 4 gates.
// B tile row r <-> W row (r>>5)*512 + nbase + (r&31). ni fragment = gate.
// A loads bypass L1 (__ldcg): cross-block state inside persistent kernels.
// ============================================================
__device__ __forceinline__ void gates_mma(
    float c[4][4][4],
    const __nv_bfloat16* A0, const int* map0, int ms0, const __nv_bfloat16* W0, int ldw0,
    const __nv_bfloat16* A1, const __nv_bfloat16* W1, int ldw1,
    const __nv_bfloat16* A2, const __nv_bfloat16* W2, int ldw2,
    int npairs, int nbase,
    __nv_bfloat16* As, __nv_bfloat16* Bs)
{
    const int tid = threadIdx.x;
    const int lane = tid & 31;
    const int wid = tid >> 5;
    const int m0 = (wid >> 2) * 64;
    const int warp_n = wid & 3;

#pragma unroll
    for (int mi = 0; mi < 4; mi++)
#pragma unroll
        for (int ni = 0; ni < 4; ni++)
#pragma unroll
            for (int q = 0; q < 4; q++) c[mi][ni][q] = 0.f;

    const unsigned as_base = (unsigned)__cvta_generic_to_shared(As);
    const unsigned bs_base = (unsigned)__cvta_generic_to_shared(Bs);
    const int ldrow = tid >> 3;
    const int ldc8 = (tid & 7) * 8;

    const __nv_bfloat16* Aps[3] = {A0, A1, A2};
    const __nv_bfloat16* Wps[3] = {W0, W1, W2};
    const int lws[3] = {ldw0, ldw1, ldw2};

    for (int p = 0; p < npairs; p++) {
        const __nv_bfloat16* A = Aps[p];
        const __nv_bfloat16* W = Wps[p];
        const int ldw = lws[p];
        for (int kc = 0; kc < 8; kc++) {
            int k0 = kc * 64;
            __syncthreads();
#pragma unroll
            for (int q4 = 0; q4 < 4; q4++) {
                int row = q4 * 32 + ldrow;
                long arow = (p == 0 && map0) ? (long)map0[row * ms0] * 512 : (long)row * 512;
                *reinterpret_cast<uint4*>(&As[row * LSTRIDE + ldc8]) =
                    __ldcg(reinterpret_cast<const uint4*>(&A[arow + k0 + ldc8]));
                int wrow = ((row >> 5) * 512) + nbase + (row & 31);
                *reinterpret_cast<uint4*>(&Bs[row * LSTRIDE + ldc8]) =
                    __ldg(reinterpret_cast<const uint4*>(&W[(long)wrow * ldw + k0 + ldc8]));
            }
            __syncthreads();
#pragma unroll
            for (int ks = 0; ks < 4; ks++) {
                int koff = ks * 16;
                unsigned int a[4][4], b[4][2];
#pragma unroll
                for (int mi = 0; mi < 4; mi++) {
                    int r = m0 + mi * 16 + (lane & 15);
                    int ccol = koff + (lane >> 4) * 8;
                    ldsm4(a[mi], as_base + (unsigned)(r * LSTRIDE + ccol) * 2u);
                }
#pragma unroll
                for (int ni = 0; ni < 4; ni++) {
                    int r = ni * 32 + warp_n * 8 + (lane & 7);
                    int ccol = koff + ((lane >> 3) & 1) * 8;
                    ldsm2(b[ni], bs_base + (unsigned)(r * LSTRIDE + ccol) * 2u);
                }
#pragma unroll
                for (int mi = 0; mi < 4; mi++)
#pragma unroll
                    for (int ni = 0; ni < 4; ni++) mma16816(c[mi][ni], a[mi], b[ni]);
            }
        }
    }
}

// ---------------- LSTM cell epilogue (4 gates in-thread) ----------------
__device__ __forceinline__ void cell_epi(
    float c[4][4][4], int nbase,
    const float* initp, long initStride, const float* bias,
    const int* lens, int t,
    const __nv_bfloat16* hbf_in, __nv_bfloat16* hbf_out,
    float* c_f, __nv_bfloat16* nh_bf_out, float* S_out, float* h_f_out)
{
    const int lane = threadIdx.x & 31;
    const int wid = threadIdx.x >> 5;
    const int m0 = (wid >> 2) * 64;
    const int warp_n = wid & 3;

#pragma unroll
    for (int mi = 0; mi < 4; mi++) {
#pragma unroll
        for (int t2 = 0; t2 < 2; t2++) {
            int row = m0 + mi * 16 + (lane >> 2) + 8 * t2;
#pragma unroll
            for (int u = 0; u < 2; u++) {
                int j = nbase + warp_n * 8 + 2 * (lane & 3) + u;
                int e = 2 * t2 + u;
                float gi = c[mi][0][e], gf = c[mi][1][e], gg = c[mi][2][e], go = c[mi][3][e];
                if (initp) {
                    const float* ip = initp + (long)row * initStride;
                    gi += ip[j]; gf += ip[512 + j]; gg += ip[1024 + j]; go += ip[1536 + j];
                }
                if (bias) {
                    gi += bias[j]; gf += bias[512 + j]; gg += bias[1024 + j]; go += bias[1536 + j];
                }
                float i_ = 1.f / (1.f + expf(-gi));
                float f_ = 1.f / (1.f + expf(-gf));
                float tg = tanhf(gg);
                float o_ = 1.f / (1.f + expf(-go));
                int idx = row * 512 + j;
                float cn = f_ * c_f[idx] + i_ * tg;
                float hn = o_ * tanhf(cn);
                bool mk = lens ? (t < lens[row]) : true;
                if (nh_bf_out) nh_bf_out[idx] = __float2bfloat16_rn(hn);
                if (S_out) S_out[(long)row * Lq * 512 + (long)t * 512 + j] = mk ? hn : 0.f;
                if (h_f_out) h_f_out[idx] = hn;
                if (mk) { c_f[idx] = cn; hbf_out[idx] = __float2bfloat16_rn(hn); }
                else hbf_out[idx] = hbf_in[idx];
            }
        }
    }
}

// ---------------- 128x128 HMMA tile (for hid inside persistent kernel) ----------------
__device__ __forceinline__ void hgemm_tile(
    float c[4][4][4],
    const __nv_bfloat16* A0, const __nv_bfloat16* W0, int ldw0,
    const __nv_bfloat16* A1, const __nv_bfloat16* W1, int ldw1,
    int nblk0, __nv_bfloat16* As, __nv_bfloat16* Bs)
{
    const int tid = threadIdx.x;
    const int lane = tid & 31;
    const int wid = tid >> 5;
    const int m0 = (wid >> 2) * 64;
    const int warp_n = wid & 3;

#pragma unroll
    for (int mi = 0; mi < 4; mi++)
#pragma unroll
        for (int ni = 0; ni < 4; ni++)
#pragma unroll
            for (int q = 0; q < 4; q++) c[mi][ni][q] = 0.f;

    const unsigned as_base = (unsigned)__cvta_generic_to_shared(As);
    const unsigned bs_base = (unsigned)__cvta_generic_to_shared(Bs);
    const int ldrow = tid >> 3;
    const int ldc8 = (tid & 7) * 8;

    const __nv_bfloat16* Aps[2] = {A0, A1};
    const __nv_bfloat16* Wps[2] = {W0, W1};
    const int lws[2] = {ldw0, ldw1};

    for (int p = 0; p < 2; p++) {
        const __nv_bfloat16* A = Aps[p];
        const __nv_bfloat16* W = Wps[p];
        const int ldw = lws[p];
        for (int kc = 0; kc < 8; kc++) {
            int k0 = kc * 64;
            __syncthreads();
#pragma unroll
            for (int q4 = 0; q4 < 4; q4++) {
                int row = q4 * 32 + ldrow;
                *reinterpret_cast<uint4*>(&As[row * LSTRIDE + ldc8]) =
                    __ldcg(reinterpret_cast<const uint4*>(&A[(long)row * 512 + k0 + ldc8]));
                *reinterpret_cast<uint4*>(&Bs[row * LSTRIDE + ldc8]) =
                    __ldg(reinterpret_cast<const uint4*>(&W[(long)(nblk0 + row) * ldw + k0 + ldc8]));
            }
            __syncthreads();
#pragma unroll
            for (int ks = 0; ks < 4; ks++) {
                int koff = ks * 16;
                unsigned int a[4][4], b[4][2];
#pragma unroll
                for (int mi = 0; mi < 4; mi++) {
                    int r = m0 + mi * 16 + (lane & 15);
                    int ccol = koff + (lane >> 4) * 8;
                    ldsm4(a[mi], as_base + (unsigned)(r * LSTRIDE + ccol) * 2u);
                }
#pragma unroll
                for (int ni = 0; ni < 4; ni++) {
                    int r = warp_n * 32 + ni * 8 + (lane & 7);
                    int ccol = koff + ((lane >> 3) & 1) * 8;
                    ldsm2(b[ni], bs_base + (unsigned)(r * LSTRIDE + ccol) * 2u);
                }
#pragma unroll
                for (int mi = 0; mi < 4; mi++)
#pragma unroll
                    for (int ni = 0; ni < 4; ni++) mma16816(c[mi][ni], a[mi], b[ni]);
            }
        }
    }
}

__device__ __forceinline__ void hid_epi(
    float c[4][4][4], int nblk0, const float* bias, __nv_bfloat16* outBF)
{
    const int lane = threadIdx.x & 31;
    const int wid = threadIdx.x >> 5;
    const int m0 = (wid >> 2) * 64;
    const int warp_n = wid & 3;
#pragma unroll
    for (int mi = 0; mi < 4; mi++)
#pragma unroll
        for (int ni = 0; ni < 4; ni++)
#pragma unroll
            for (int t2 = 0; t2 < 2; t2++) {
                int gm = m0 + mi * 16 + (lane >> 2) + 8 * t2;
#pragma unroll
                for (int u = 0; u < 2; u++) {
                    int n = nblk0 + warp_n * 32 + ni * 8 + 2 * (lane & 3) + u;
                    float v = c[mi][ni][2 * t2 + u] + bias[n];
                    outBF[(long)gm * Hq + n] = __float2bfloat16_rn(v);
                }
            }
}

// ---------------- attention: 8 batch rows per block ----------------
__device__ void attn8(int rb0, const int* slens, char* raw)
{
    float* sh = (float*)raw;        // 512
    float* part = sh + 512;         // 256
    float* sc = part + 256;         // 64
    float* sinv = sc + 64;          // 1
    int tid = threadIdx.x;
    for (int r = 0; r < 8; r++) {
        int b = rb0 + r;
        __syncthreads();
        sh[tid] = __ldcg(&g_dh[(long)b * Hq + tid]);
        sh[tid + 256] = __ldcg(&g_dh[(long)b * Hq + tid + 256]);
        __syncthreads();
        int l = tid >> 2, q = tid & 3;
        const float* Sb = g_S + (long)b * Lq * Hq + (long)l * Hq + q * 128;
        float pv = 0.f;
#pragma unroll 8
        for (int k = 0; k < 128; k++) pv = fmaf(sh[q * 128 + k], Sb[k], pv);
        part[l * 4 + q] = pv;
        __syncthreads();
        if (tid < Lq) {
            float sv = part[tid * 4] + part[tid * 4 + 1] + part[tid * 4 + 2] + part[tid * 4 + 3];
            if (tid >= slens[b]) sv = -1e9f;
            sc[tid] = __expf(sv);
        }
        __syncthreads();
        if (tid == 0) {
            float ts = 0.f;
            for (int i = 0; i < Lq; i++) ts += sc[i];
            *sinv = 1.f / ts;
        }
        __syncthreads();
        if (tid < Lq) sc[tid] *= *sinv;
        __syncthreads();
        for (int j = tid; j < Hq; j += 256) {
            const float* Sb2 = g_S + (long)b * Lq * Hq + j;
            float acc = 0.f;
#pragma unroll 8
            for (int l2 = 0; l2 < Lq; l2++) acc = fmaf(sc[l2], Sb2[(long)l2 * Hq], acc);
            g_ctxb[(long)b * Hq + j] = __float2bfloat16_rn(acc);
        }
    }
}

// ---------------- logits tile: GEMM + bias + exp-sum + target capture ----------------
__device__ void logits_tile(
    int tl, const __nv_bfloat16* avh, const float* out_b,
    const int* stgt, float* red, __nv_bfloat16* As, __nv_bfloat16* Bs)
{
    const int tid = threadIdx.x;
    const int lane = tid & 31;
    const int wid = tid >> 5;
    const int m0 = (wid >> 2) * 64;
    const int warp_n = wid & 3;
    const int n0w = warp_n * 32;
    const int nblk0 = tl * 128;

    float c[4][4][4];
#pragma unroll
    for (int mi = 0; mi < 4; mi++)
#pragma unroll
        for (int ni = 0; ni < 4; ni++)
#pragma unroll
            for (int q = 0; q < 4; q++) c[mi][ni][q] = 0.f;

    const unsigned as_base = (unsigned)__cvta_generic_to_shared(As);
    const unsigned bs_base = (unsigned)__cvta_generic_to_shared(Bs);
    const int ldrow = tid >> 3;
    const int ldc8 = (tid & 7) * 8;

    for (int kc = 0; kc < 8; kc++) {
        int k0 = kc * 64;
        __syncthreads();
#pragma unroll
        for (int q4 = 0; q4 < 4; q4++) {
            int row = q4 * 32 + ldrow;
            *reinterpret_cast<uint4*>(&As[row * LSTRIDE + ldc8]) =
                __ldcg(reinterpret_cast<const uint4*>(&avh[row * KP + k0 + ldc8]));
            *reinterpret_cast<uint4*>(&Bs[row * LSTRIDE + ldc8]) =
                __ldg(reinterpret_cast<const uint4*>(&g_outWb[(long)(nblk0 + row) * KP + k0 + ldc8]));
        }
        __syncthreads();
#pragma unroll
        for (int ks = 0; ks < 4; ks++) {
            int koff = ks * 16;
            unsigned int a[4][4], b[4][2];
#pragma unroll
            for (int mi = 0; mi < 4; mi++) {
                int r = m0 + mi * 16 + (lane & 15);
                int ccol = koff + (lane >> 4) * 8;
                ldsm4(a[mi], as_base + (unsigned)(r * LSTRIDE + ccol) * 2u);
            }
#pragma unroll
            for (int ni = 0; ni < 4; ni++) {
                int r = n0w + ni * 8 + (lane & 7);
                int ccol = koff + ((lane >> 3) & 1) * 8;
                ldsm2(b[ni], bs_base + (unsigned)(r * LSTRIDE + ccol) * 2u);
            }
#pragma unroll
            for (int mi = 0; mi < 4; mi++)
#pragma unroll
                for (int ni = 0; ni < 4; ni++) mma16816(c[mi][ni], a[mi], b[ni]);
        }
    }
    __syncthreads();

    const int gid = lane >> 2;
    const int tig = lane & 3;
#pragma unroll
    for (int mi = 0; mi < 4; mi++) {
        int r0 = m0 + mi * 16 + gid;
        int r1 = r0 + 8;
        int t0 = stgt[r0], t1 = stgt[r1];
        float s0 = 0.f, s1 = 0.f;
#pragma unroll
        for (int ni = 0; ni < 4; ni++) {
            int n = nblk0 + n0w + ni * 8 + tig * 2;
            float b0 = out_b[n], b1 = out_b[n + 1];
            float l00 = c[mi][ni][0] + b0, l01 = c[mi][ni][1] + b1;
            float l10 = c[mi][ni][2] + b0, l11 = c[mi][ni][3] + b1;
            s0 += __expf(l00) + __expf(l01);
            s1 += __expf(l10) + __expf(l11);
            if (n == t0) g_tgtlogit[r0] = l00;
            if (n + 1 == t0) g_tgtlogit[r0] = l01;
            if (n == t1) g_tgtlogit[r1] = l10;
            if (n + 1 == t1) g_tgtlogit[r1] = l11;
        }
        s0 += __shfl_xor_sync(0xffffffffu, s0, 1);
        s0 += __shfl_xor_sync(0xffffffffu, s0, 2);
        s1 += __shfl_xor_sync(0xffffffffu, s1, 1);
        s1 += __shfl_xor_sync(0xffffffffu, s1, 2);
        if (tig == 0) { red[r0 * 4 + warp_n] = s0; red[r1 * 4 + warp_n] = s1; }
    }
    __syncthreads();
    if (tid < 128)
        g_part[tl * Bq + tid] = red[tid * 4] + red[tid * 4 + 1] + red[tid * 4 + 2] + red[tid * 4 + 3];
}

__device__ void combine_row(int b, int s, const int* trg_lens, float* red)
{
    int tid = threadIdx.x;
    float acc = 0.f;
    for (int i = tid; i < NTILES; i += 256) acc += __ldcg(&g_part[i * Bq + b]);
    red[tid] = acc;
    __syncthreads();
    for (int st = 128; st > 0; st >>= 1) {
        if (tid < st) red[tid] += red[tid + st];
        __syncthreads();
    }
    if (tid == 0) {
        float nll = logf(red[0]) - __ldcg(&g_tgtlogit[b]);
        g_nllbuf[s * Bq + b] = ((s + 1) < trg_lens[b]) ? -nll : 0.f;
    }
}

// ============================================================
// persistent encoder: 16 blocks, 64 steps x 2 layers
// ============================================================
__global__ __launch_bounds__(256) void enc_persist_k(const int* __restrict__ src_lens,
                                                     const float* __restrict__ enc_b1)
{
    __shared__ __align__(16) char raw[40960];
    __nv_bfloat16* As = (__nv_bfloat16*)raw;
    __nv_bfloat16* Bs = As + 128 * LSTRIDE;
    const int nbase = blockIdx.x * 32;
    float c[4][4][4];
    unsigned gen = 0;
    for (int t = 0; t < Lq; t++) {
        int p = t & 1;
        gates_mma(c, g_h1b[p], nullptr, 0, g_Whh0b, 512,
                  nullptr, nullptr, 0, nullptr, nullptr, 0, 1, nbase, As, Bs);
        cell_epi(c, nbase, g_G0 + (long)t * G4, (long)Lq * G4, nullptr, src_lens, t,
                 g_h1b[p], g_h1b[1 - p], g_c1, g_nh1b, nullptr, nullptr);
        gen++; gbar(&g_sync[0], 16u * gen);
        gates_mma(c, g_nh1b, nullptr, 0, g_Wih1b, 512,
                  g_h2b[p], g_Whh1b, 512, nullptr, nullptr, 0, 2, nbase, As, Bs);
        cell_epi(c, nbase, nullptr, 0, enc_b1, src_lens, t,
                 g_h2b[p], g_h2b[1 - p], g_c2, nullptr, g_S, nullptr);
        gen++; gbar(&g_sync[0], 16u * gen);
    }
}

// ============================================================
// persistent decoder: 148 blocks = 16 recurrent + 132 logits
// ============================================================
__global__ __launch_bounds__(256) void dec_persist_k(
    const int* __restrict__ trg_tokens, const int* __restrict__ trg_lens,
    const int* __restrict__ src_lens,
    const float* __restrict__ dec_b, const float* __restrict__ hid_b,
    const float* __restrict__ out_b)
{
    __shared__ __align__(16) char raw[40960];
    __nv_bfloat16* As = (__nv_bfloat16*)raw;
    __nv_bfloat16* Bs = As + 128 * LSTRIDE;
    const int blk = blockIdx.x;
    const int tid = threadIdx.x;

    if (blk < 16) {
        // ---- recurrent group ----
        float c[4][4][4];
        const int nbase = blk * 32;
        unsigned gen = 0;
        for (int s = 0; s < Tq - 1; s++) {
            int p = s & 1;
            gates_mma(c, g_trgEmbB, trg_tokens + s, Tq, g_dWihb, 1024,
                      g_avh[p], g_dWihb + 512, 1024,
                      g_dhb[p], g_dWhhb, 512, 3, nbase, As, Bs);
            cell_epi(c, nbase, nullptr, 0, dec_b, nullptr, 0,
                     g_dhb[p], g_dhb[1 - p], g_dc, nullptr, nullptr, g_dh);
            gen++; gbar(&g_sync[8], 16u * gen);

            attn8(blk * 8, src_lens, raw);
            gen++; gbar(&g_sync[8], 16u * gen);

            if (blk < 4) {
                if (s >= 2) wait_ge(&g_sync[32], (unsigned)(s - 1));
                hgemm_tile(c, g_dhb[(s + 1) & 1], g_hidWb, 1024,
                           g_ctxb, g_hidWb + 512, 1024, blk * 128, As, Bs);
                hid_epi(c, blk * 128, hid_b, g_avh[(s + 1) & 1]);
            }
            gen++; gbar(&g_sync[8], 16u * gen);
            if (blk == 0 && tid == 0) set_flag(&g_sync[24], (unsigned)(s + 1));
        }
    } else {
        // ---- logits group ----
        const int lb = blk - 16;
        int* stgt = (int*)(raw + 36864);
        float* red = (float*)(raw + 36864 + 512);
        unsigned gen = 0;
        for (int s = 0; s < Tq - 1; s++) {
            wait_ge(&g_sync[24], (unsigned)(s + 1));
            if (tid < 128) stgt[tid] = trg_tokens[tid * Tq + s + 1];
            __syncthreads();
            for (int w = 0; w < 2; w++) {
                int tl = lb + NLBLK * w;
                if (tl < NTILES)
                    logits_tile(tl, g_avh[(s + 1) & 1], out_b, stgt, red, As, Bs);
            }
            gen++; gbar(&g_sync[16], (unsigned)NLBLK * gen);
            if (lb < 128) combine_row(lb, s, trg_lens, red);
            gen++; gbar(&g_sync[16], (unsigned)NLBLK * gen);
            if (lb == 0 && tid == 0) set_flag(&g_sync[32], (unsigned)(s + 1));
        }
    }
}

// ============================================================
// standalone bf16 GEMM (G0 + decoder-init) — unchanged from R5
// ============================================================
__global__ __launch_bounds__(256) void hgemm_k(
    const __nv_bfloat16* __restrict__ A0, const int* __restrict__ map0, int ms0,
    const __nv_bfloat16* __restrict__ W0, int ldw0,
    const __nv_bfloat16* __restrict__ A1, const __nv_bfloat16* __restrict__ W1, int ldw1,
    int npairs,
    const float* __restrict__ bias, int N,
    float* __restrict__ outRaw, float* __restrict__ outTanhF,
    __nv_bfloat16* __restrict__ outBF)
{
    __shared__ __nv_bfloat16 As[128 * LSTRIDE];
    __shared__ __nv_bfloat16 Bs[128 * LSTRIDE];

    const int tid = threadIdx.x;
    const int lane = tid & 31;
    const int wid = tid >> 5;
    const int warp_n = wid & 3;
    const int m0 = (wid >> 2) * 64;
    const int mblk0 = blockIdx.x * 128;
    const int nblk0 = blockIdx.y * 128;

    float c[4][4][4];
#pragma unroll
    for (int mi = 0; mi < 4; mi++)
#pragma unroll
        for (int ni = 0; ni < 4; ni++)
#pragma unroll
            for (int q = 0; q < 4; q++) c[mi][ni][q] = 0.f;

    const unsigned as_base = (unsigned)__cvta_generic_to_shared(As);
    const unsigned bs_base = (unsigned)__cvta_generic_to_shared(Bs);
    const int ldrow = tid >> 3;
    const int ldc8 = (tid & 7) * 8;

    const __nv_bfloat16* Aps[2] = {A0, A1};
    const __nv_bfloat16* Wps[2] = {W0, W1};
    const int lws[2] = {ldw0, ldw1};

    for (int p = 0; p < npairs; p++) {
        const __nv_bfloat16* A = Aps[p];
        const __nv_bfloat16* W = Wps[p];
        const int ldw = lws[p];
        for (int kc = 0; kc < 8; kc++) {
            int k0 = kc * 64;
            __syncthreads();
#pragma unroll
            for (int q4 = 0; q4 < 4; q4++) {
                int row = q4 * 32 + ldrow;
                int gm = mblk0 + row;
                long arow = (p == 0 && map0) ? (long)map0[gm * ms0] * 512 : (long)gm * 512;
                *reinterpret_cast<uint4*>(&As[row * LSTRIDE + ldc8]) =
                    *reinterpret_cast<const uint4*>(&A[arow + k0 + ldc8]);
                *reinterpret_cast<uint4*>(&Bs[row * LSTRIDE + ldc8]) =
                    *reinterpret_cast<const uint4*>(&W[(long)(nblk0 + row) * ldw + k0 + ldc8]);
            }
            __syncthreads();
#pragma unroll
            for (int ks = 0; ks < 4; ks++) {
                int koff = ks * 16;
                unsigned int a[4][4], b[4][2];
#pragma unroll
                for (int mi = 0; mi < 4; mi++) {
                    int r = m0 + mi * 16 + (lane & 15);
                    int ccol = koff + (lane >> 4) * 8;
                    ldsm4(a[mi], as_base + (unsigned)(r * LSTRIDE + ccol) * 2u);
                }
#pragma unroll
                for (int ni = 0; ni < 4; ni++) {
                    int r = warp_n * 32 + ni * 8 + (lane & 7);
                    int ccol = koff + ((lane >> 3) & 1) * 8;
                    ldsm2(b[ni], bs_base + (unsigned)(r * LSTRIDE + ccol) * 2u);
                }
#pragma unroll
                for (int mi = 0; mi < 4; mi++)
#pragma unroll
                    for (int ni = 0; ni < 4; ni++) mma16816(c[mi][ni], a[mi], b[ni]);
            }
        }
    }

#pragma unroll
    for (int mi = 0; mi < 4; mi++)
#pragma unroll
        for (int ni = 0; ni < 4; ni++)
#pragma unroll
            for (int t2 = 0; t2 < 2; t2++) {
                int gm = mblk0 + m0 + mi * 16 + (lane >> 2) + 8 * t2;
#pragma unroll
                for (int u = 0; u < 2; u++) {
                    int n = nblk0 + warp_n * 32 + ni * 8 + 2 * (lane & 3) + u;
                    float v = c[mi][ni][2 * t2 + u];
                    if (bias) v += bias[n];
                    long oi = (long)gm * N + n;
                    if (outRaw) outRaw[oi] = v;
                    float tv = v;
                    if (outTanhF) { tv = tanhf(v); outTanhF[oi] = tv; }
                    if (outBF) outBF[oi] = __float2bfloat16_rn(outTanhF ? tv : v);
                }
            }
}

// ---------------- misc ----------------
__global__ void zero_k()
{
    int i = blockIdx.x * 256 + threadIdx.x;
    if (blockIdx.x == 0 && threadIdx.x < 64) g_sync[threadIdx.x] = 0u;
    if (i < HB) {
        g_h1b[0][i] = __float2bfloat16(0.f);
        g_h2b[0][i] = __float2bfloat16(0.f);
        g_avh[0][i] = __float2bfloat16(0.f);
        g_c1[i] = 0.f; g_c2[i] = 0.f;
    }
}

__global__ void f2bf_k(const float* __restrict__ in, __nv_bfloat16* __restrict__ out, int n)
{
    int i = blockIdx.x * 256 + threadIdx.x;
    if (i < n) out[i] = __float2bfloat16_rn(in[i]);
}

__global__ __launch_bounds__(256) void reduce_k(float* __restrict__ out)
{
    __shared__ float sm[256];
    float t = 0.f;
    for (int i = threadIdx.x; i < (Tq - 1) * Bq; i += 256) t += g_nllbuf[i];
    sm[threadIdx.x] = t;
    __syncthreads();
    for (int st = 128; st > 0; st >>= 1) {
        if (threadIdx.x < st) sm[threadIdx.x] += sm[threadIdx.x + st];
        __syncthreads();
    }
    if (threadIdx.x == 0) out[0] = sm[0];
}

// ---------------- launch ----------------
extern "C" void kernel_launch(void* const* d_in, const int* in_sizes, int n_in,
                              void* d_out, int out_size)
{
    const int*   src_tokens = (const int*)d_in[0];
    const int*   src_lens   = (const int*)d_in[1];
    const int*   trg_tokens = (const int*)d_in[2];
    const int*   trg_lens   = (const int*)d_in[3];
    const float* src_emb    = (const float*)d_in[4];
    const float* trg_emb    = (const float*)d_in[5];
    const float* enc_Wih0   = (const float*)d_in[6];
    const float* enc_Whh0   = (const float*)d_in[7];
    const float* enc_b0     = (const float*)d_in[8];
    const float* enc_Wih1   = (const float*)d_in[9];
    const float* enc_Whh1   = (const float*)d_in[10];
    const float* enc_b1     = (const float*)d_in[11];
    const float* dec_Wih    = (const float*)d_in[12];
    const float* dec_Whh    = (const float*)d_in[13];
    const float* dec_b      = (const float*)d_in[14];
    const float* hid_W      = (const float*)d_in[15];
    const float* hid_b      = (const float*)d_in[16];
    const float* out_W      = (const float*)d_in[17];
    const float* out_b      = (const float*)d_in[18];
    const float* init_W     = (const float*)d_in[19];
    const float* init_b     = (const float*)d_in[20];

    float *G0, *c1, *c2, *dc, *dh;
    __nv_bfloat16 *Wih0b, *Whh0b, *Wih1b, *Whh1b, *dWihb, *dWhhb, *hidWb, *initWb;
    __nv_bfloat16 *srcEmbB, *trgEmbB, *outWb, *c1b, *c2b, *dhb0;
    cudaGetSymbolAddress((void**)&G0, g_G0);
    cudaGetSymbolAddress((void**)&c1, g_c1);
    cudaGetSymbolAddress((void**)&c2, g_c2);
    cudaGetSymbolAddress((void**)&dc, g_dc);
    cudaGetSymbolAddress((void**)&dh, g_dh);
    cudaGetSymbolAddress((void**)&Wih0b, g_Wih0b);
    cudaGetSymbolAddress((void**)&Whh0b, g_Whh0b);
    cudaGetSymbolAddress((void**)&Wih1b, g_Wih1b);
    cudaGetSymbolAddress((void**)&Whh1b, g_Whh1b);
    cudaGetSymbolAddress((void**)&dWihb, g_dWihb);
    cudaGetSymbolAddress((void**)&dWhhb, g_dWhhb);
    cudaGetSymbolAddress((void**)&hidWb, g_hidWb);
    cudaGetSymbolAddress((void**)&initWb, g_initWb);
    cudaGetSymbolAddress((void**)&srcEmbB, g_srcEmbB);
    cudaGetSymbolAddress((void**)&trgEmbB, g_trgEmbB);
    cudaGetSymbolAddress((void**)&outWb, g_outWb);
    cudaGetSymbolAddress((void**)&c1b, g_c1b);
    cudaGetSymbolAddress((void**)&c2b, g_c2b);
    cudaGetSymbolAddress((void**)&dhb0, g_dhb);

    const int cb = (HB + 255) / 256;

    zero_k<<<cb, 256>>>();

    f2bf_k<<<(G4 * KP + 255) / 256, 256>>>(enc_Wih0, Wih0b, G4 * KP);
    f2bf_k<<<(G4 * KP + 255) / 256, 256>>>(enc_Whh0, Whh0b, G4 * KP);
    f2bf_k<<<(G4 * KP + 255) / 256, 256>>>(enc_Wih1, Wih1b, G4 * KP);
    f2bf_k<<<(G4 * KP + 255) / 256, 256>>>(enc_Whh1, Whh1b, G4 * KP);
    f2bf_k<<<(G4 * 1024 + 255) / 256, 256>>>(dec_Wih, dWihb, G4 * 1024);
    f2bf_k<<<(G4 * KP + 255) / 256, 256>>>(dec_Whh, dWhhb, G4 * KP);
    f2bf_k<<<(Hq * 1024 + 255) / 256, 256>>>(hid_W, hidWb, Hq * 1024);
    f2bf_k<<<(Hq * 1024 + 255) / 256, 256>>>(init_W, initWb, Hq * 1024);
    f2bf_k<<<(Vq * Eq + 255) / 256, 256>>>(src_emb, srcEmbB, Vq * Eq);
    f2bf_k<<<(Vq * Eq + 255) / 256, 256>>>(trg_emb, trgEmbB, Vq * Eq);
    f2bf_k<<<(Vq * KP + 255) / 256, 256>>>(out_W, outWb, Vq * KP);

    // G0 = emb(src) @ Wih0^T + b0
    hgemm_k<<<dim3(Bq * Lq / 128, G4 / 128), 256>>>(
        srcEmbB, src_tokens, 1, Wih0b, KP,
        nullptr, nullptr, 0, 1,
        enc_b0, G4, G0, nullptr, nullptr);

    // persistent encoder
    enc_persist_k<<<16, 256>>>(src_lens, enc_b1);

    // decoder init: c0 = [c1,c2] @ init_W^T + init_b ; h0 = tanh(c0)
    f2bf_k<<<cb, 256>>>(c1, c1b, HB);
    f2bf_k<<<cb, 256>>>(c2, c2b, HB);
    hgemm_k<<<dim3(1, Hq / 128), 256>>>(
        c1b, nullptr, 0, initWb, 1024,
        c2b, initWb + 512, 1024, 2,
        init_b, Hq, dc, dh, dhb0);

    // persistent decoder (16 recurrent blocks + 132 logits blocks)
    dec_persist_k<<<148, 256>>>(trg_tokens, trg_lens, src_lens, dec_b, hid_b, out_b);

    reduce_k<<<1, 256>>>((float*)d_out);
}